// round 15
// baseline (speedup 1.0000x reference)
#include <cuda_runtime.h>
#include <cuda_fp16.h>

#define BDIM 2
#define NSEQ 2048
#define DMODEL 256
#define HHEADS 8
#define DH 32
#define MROWS (BDIM*NSEQ)   // 4096
#define NBH (BDIM*HHEADS)   // 16

#define LOG2E 1.4426950408889634
#define QSCALE ((float)(1.4426950408889634/5.656854249492381))  // log2e/sqrt(32)

typedef unsigned long long u64;
typedef unsigned int u32;

// ---------------- scratch (__device__ globals; no allocations) --------------
__device__ __align__(16) __half g_Qhi[NBH*NSEQ*DH];
__device__ __align__(16) __half g_Qlo[NBH*NSEQ*DH];
__device__ __align__(16) __half g_Khi[NBH*NSEQ*DH];          // K: single fp16
__device__ __align__(16) __half g_Vhi[NBH*NSEQ*DH];          // V: single fp16
__device__ __align__(16) __half g_Ohi[MROWS*DMODEL];
__device__ __align__(16) __half g_Olo[MROWS*DMODEL];
__device__ __align__(16) __half g_wh[4*DMODEL*DMODEL];       // q,k,v,o  (single fp16)

// ---------------- helpers ---------------------------------------------------
__device__ __forceinline__ u32 smem_u32(const void* p) {
    u32 a; asm("{ .reg .u64 t; cvta.to.shared.u64 t, %1; cvt.u32.u64 %0, t; }" : "=r"(a) : "l"(p));
    return a;
}
__device__ __forceinline__ void ldsm4(u32 &r0, u32 &r1, u32 &r2, u32 &r3, u32 a) {
    asm volatile("ldmatrix.sync.aligned.m8n8.x4.shared.b16 {%0,%1,%2,%3}, [%4];"
                 : "=r"(r0), "=r"(r1), "=r"(r2), "=r"(r3) : "r"(a));
}
__device__ __forceinline__ void ldsm4t(u32 &r0, u32 &r1, u32 &r2, u32 &r3, u32 a) {
    asm volatile("ldmatrix.sync.aligned.m8n8.x4.trans.shared.b16 {%0,%1,%2,%3}, [%4];"
                 : "=r"(r0), "=r"(r1), "=r"(r2), "=r"(r3) : "r"(a));
}
__device__ __forceinline__ void mma16816(float* d, const u32* a, u32 b0, u32 b1) {
    asm volatile("mma.sync.aligned.m16n8k16.row.col.f32.f16.f16.f32 "
                 "{%0,%1,%2,%3}, {%4,%5,%6,%7}, {%8,%9}, {%0,%1,%2,%3};"
                 : "+f"(d[0]), "+f"(d[1]), "+f"(d[2]), "+f"(d[3])
                 : "r"(a[0]), "r"(a[1]), "r"(a[2]), "r"(a[3]), "r"(b0), "r"(b1));
}
__device__ __forceinline__ float ex2(float x) {
    float r; asm("ex2.approx.ftz.f32 %0, %1;" : "=f"(r) : "f"(x)); return r;
}
__device__ __forceinline__ u32 packh(float a, float b) {
    __half2 t = __floats2half2_rn(a, b);     // low = a
    return *(u32*)&t;
}
__device__ __forceinline__ u32 packsplith(float v0, float v1, u32 &lw) {
    u32 hw = packh(v0, v1);
    __half2 hv = *(__half2*)&hw;
    float e0 = __half2float(__low2half(hv));
    float e1 = __half2float(__high2half(hv));
    lw = packh(v0 - e0, v1 - e1);
    return hw;
}
__device__ __forceinline__ void cpa16(u32 dst, const void* src) {
    asm volatile("cp.async.cg.shared.global [%0], [%1], 16;" :: "r"(dst), "l"(src) : "memory");
}
#define CPA_COMMIT() asm volatile("cp.async.commit_group;" ::: "memory")
#define CPA_WAIT0()  asm volatile("cp.async.wait_group 0;" ::: "memory")

// ---------------------------------------------------------------------------
// Convert fp32 -> fp16 weights (single fp16), 4 matrices. grid (128,1,4).
// ---------------------------------------------------------------------------
__global__ __launch_bounds__(256) void convert_w(
    const float* __restrict__ Wq, const float* __restrict__ Wk,
    const float* __restrict__ Wv, const float* __restrict__ Wo)
{
    const int z = blockIdx.z;
    const float* src = (z == 0) ? Wq : (z == 1) ? Wk : (z == 2) ? Wv : Wo;
    __half* dh = g_wh + (size_t)z * DMODEL * DMODEL;
    int i = (blockIdx.x * 256 + threadIdx.x) * 2;
    if (i >= DMODEL * DMODEL) return;
    float2 v = *(const float2*)(src + i);
    *(u32*)(dh + i) = packh(v.x, v.y);
}

// ---------------------------------------------------------------------------
// Tensor-core projection: C = X @ W^T + bias, fp16 2-term (Xhi+Xlo)*Whi.
// mode 0=Q (scaled, hi/lo out), 1=K (hi out), 2=V (hi out), 3=out (fp32).
// BM=64, BN=32, BK=32. 256 thr / 8 warps (4 row-grp x 2 col-grp of 16).
// ---------------------------------------------------------------------------
#define PRB 80       // smem row stride bytes (64B data + pad)
#define PXH 0
#define PXL 5120
#define PWH 10240    // W region: 32 rows x 80B = 2560B

__global__ __launch_bounds__(256, 3) void proj_tc(
    const float* __restrict__ x,
    const float* __restrict__ bq, const float* __restrict__ bk,
    const float* __restrict__ bv, const float* __restrict__ bo,
    float* __restrict__ outf, int base_mode)
{
    __shared__ __align__(128) char sm[12800];
    const u32 sb = smem_u32(sm);
    const int mode = base_mode + blockIdx.z;
    const __half* Wh = g_wh + (size_t)mode * DMODEL * DMODEL;
    const float* bias = (mode == 0) ? bq : (mode == 1) ? bk : (mode == 2) ? bv : bo;

    const int tid = threadIdx.x, lane = tid & 31, w = tid >> 5;
    const int wr = w & 3, wc = w >> 2;
    const int row0 = blockIdx.y * 64, col0 = blockIdx.x * 32;

    const int xr = tid >> 2, xs = tid & 3;         // X staging: 64 rows x 4 chunks
    const int wrr = (tid - 128) >> 2, wss = (tid - 128) & 3;  // W: threads 128..255

    const float* px32 = x + (size_t)(row0 + xr) * DMODEL + xs * 8;
    const __half* poh = g_Ohi + (size_t)(row0 + xr) * DMODEL + xs * 8;
    const __half* pol = g_Olo + (size_t)(row0 + xr) * DMODEL + xs * 8;
    const __half* pwh = Wh + (size_t)(col0 + (tid >= 128 ? wrr : 0)) * DMODEL
                        + (tid >= 128 ? wss : 0) * 8;

    uint4 rxh, rxl, rwh;
    if (mode == 3) {
        rxh = *(const uint4*)poh; rxl = *(const uint4*)pol;
    } else {
        float4 f0 = *(const float4*)px32, f1 = *(const float4*)(px32 + 4);
        rxh.x = packsplith(f0.x, f0.y, rxl.x);
        rxh.y = packsplith(f0.z, f0.w, rxl.y);
        rxh.z = packsplith(f1.x, f1.y, rxl.z);
        rxh.w = packsplith(f1.z, f1.w, rxl.w);
    }
    if (tid >= 128) rwh = *(const uint4*)pwh;

    float acc[2][4] = {};
    const int j = lane >> 3, r = lane & 7;
    const u32 abase = sb + PXH + (u32)(16 * wr + (j & 1) * 8 + r) * PRB + (u32)(j >> 1) * 16;
    const u32 wbase = sb + PWH + (u32)(16 * wc + (lane & 15)) * PRB + (u32)(lane >> 4) * 16;

    for (int kt = 0; kt < 8; kt++) {
        __syncthreads();
        *(uint4*)(sm + PXH + xr * PRB + xs * 16) = rxh;
        *(uint4*)(sm + PXL + xr * PRB + xs * 16) = rxl;
        if (tid >= 128) *(uint4*)(sm + PWH + wrr * PRB + wss * 16) = rwh;
        __syncthreads();
        if (kt < 7) {
            int ko = (kt + 1) * 32;
            if (mode == 3) {
                rxh = *(const uint4*)(poh + ko); rxl = *(const uint4*)(pol + ko);
            } else {
                float4 f0 = *(const float4*)(px32 + ko), f1 = *(const float4*)(px32 + ko + 4);
                rxh.x = packsplith(f0.x, f0.y, rxl.x);
                rxh.y = packsplith(f0.z, f0.w, rxl.y);
                rxh.z = packsplith(f1.x, f1.y, rxl.z);
                rxh.w = packsplith(f1.z, f1.w, rxl.w);
            }
            if (tid >= 128) rwh = *(const uint4*)(pwh + ko);
        }
        u32 ah[2][4], al[2][4];
        ldsm4(ah[0][0], ah[0][1], ah[0][2], ah[0][3], abase);
        ldsm4(ah[1][0], ah[1][1], ah[1][2], ah[1][3], abase + 32);
        ldsm4(al[0][0], al[0][1], al[0][2], al[0][3], abase + (PXL - PXH));
        ldsm4(al[1][0], al[1][1], al[1][2], al[1][3], abase + (PXL - PXH) + 32);
        #pragma unroll
        for (int kc = 0; kc < 2; kc++) {
            u32 wb = wbase + kc * 32;
            u32 h0, h1, h2, h3;
            ldsm4(h0, h1, h2, h3, wb);
            mma16816(acc[0], ah[kc], h0, h2);
            mma16816(acc[0], al[kc], h0, h2);
            mma16816(acc[1], ah[kc], h1, h3);
            mma16816(acc[1], al[kc], h1, h3);
        }
    }

    // epilogue
    const int g = lane >> 2, c = lane & 3;
    const int m0 = row0 + 16 * wr + g;
    #pragma unroll
    for (int half = 0; half < 2; half++) {
        int m = m0 + 8 * half;
        int bb = m >> 11, n = m & (NSEQ - 1);
        #pragma unroll
        for (int nn = 0; nn < 2; nn++) {
            int col = col0 + 16 * wc + 8 * nn + 2 * c;
            float v0 = acc[nn][2 * half + 0] + bias[col];
            float v1 = acc[nn][2 * half + 1] + bias[col + 1];
            if (mode == 3) {
                *(float2*)(outf + (size_t)m * DMODEL + col) = make_float2(v0, v1);
            } else {
                int hh = col >> 5, d = col & 31;
                size_t idx = (((size_t)(bb * HHEADS + hh)) * NSEQ + n) * DH + d;
                if (mode == 1) {
                    *(u32*)(g_Khi + idx) = packh(v0, v1);
                } else if (mode == 2) {
                    *(u32*)(g_Vhi + idx) = packh(v0, v1);
                } else {
                    v0 *= QSCALE; v1 *= QSCALE;
                    u32 lw, hw = packsplith(v0, v1, lw);
                    *(u32*)(g_Qhi + idx) = hw;
                    *(u32*)(g_Qlo + idx) = lw;
                }
            }
        }
    }
}

// ---------------------------------------------------------------------------
// mma.sync flash attention, fp16. S = (Qhi+Qlo)*Khi; PV = Phi*Vhi.
// S accumulation split into two chains (depth 2) and merged in exp arg.
// cp.async K/V staging into double buffer; fused S->PV per 16-key chunk;
// A-tile software pipelined in registers. One __syncthreads per k-tile.
// Grid (16 q-tiles, 16 bh), 256 threads / 8 warps; warp owns 16 query rows.
// ---------------------------------------------------------------------------
#define ROWB 80
#define BUFB 10240          // bytes per K/V buffer (K 5120 + V 5120)
#define KH_OFF 0
#define VH_OFF 5120
#define NKT (NSEQ/64)       // 32 k-tiles

__global__ __launch_bounds__(256, 2) void attn_mma(
    const float* __restrict__ A,
    const float* __restrict__ W1, const float* __restrict__ b1,
    const float* __restrict__ W2, const float* __restrict__ b2)
{
    __shared__ __align__(128) char smem[2 * BUFB];
    const u32 sb = smem_u32(smem);
    const int tid = threadIdx.x;
    const int lane = tid & 31, w = tid >> 5;
    const int bh = blockIdx.y, b = bh >> 3, h = bh & 7;
    const int q0 = blockIdx.x * 128;
    const int g = lane >> 2, c = lane & 3;

    // bias MLP coefficients (log2 domain)
    bool fastp = true;
    float cpl = 0.f, cnl = 0.f;
    #pragma unroll
    for (int j = 0; j < 8; j++) {
        float w1 = W1[j], w2v = W2[h * 8 + j];
        fastp = fastp && (b1[j] == 0.0f);
        float cc = w2v * w1;
        cpl += cc * (w1 > 0.f ? 1.0f : 0.01f);
        cnl += cc * (w1 < 0.f ? 1.0f : 0.01f);
    }
    const float b2raw = b2[h];
    const float b2hl = b2raw * (float)LOG2E;
    cpl *= (float)LOG2E; cnl *= (float)LOG2E;

    // ---- stage Q: QH -> buffer0, QL -> buffer1; consume to regs ----
    {
        int row = tid >> 1, seg = tid & 1;
        const uint4* sh = (const uint4*)(g_Qhi + ((size_t)bh * NSEQ + q0 + row) * DH + seg * 16);
        const uint4* sl = (const uint4*)(g_Qlo + ((size_t)bh * NSEQ + q0 + row) * DH + seg * 16);
        uint4 h0 = sh[0], h1 = sh[1];
        uint4 l0 = sl[0], l1 = sl[1];
        char* d0 = smem + row * ROWB + seg * 32;
        *(uint4*)d0 = h0; *(uint4*)(d0 + 16) = h1;
        char* d1 = smem + BUFB + row * ROWB + seg * 32;
        *(uint4*)d1 = l0; *(uint4*)(d1 + 16) = l1;
    }
    __syncthreads();
    u32 qh[2][4], ql[2][4];
    {
        int j = lane >> 3, r = lane & 7;
        int qrow = 16 * w + (j & 1) * 8 + r;
        u32 base = sb + qrow * ROWB + (u32)(j >> 1) * 16;
        ldsm4(qh[0][0], qh[0][1], qh[0][2], qh[0][3], base);
        ldsm4(qh[1][0], qh[1][1], qh[1][2], qh[1][3], base + 32);
        ldsm4(ql[0][0], ql[0][1], ql[0][2], ql[0][3], base + BUFB);
        ldsm4(ql[1][0], ql[1][1], ql[1][2], ql[1][3], base + BUFB + 32);
    }
    __syncthreads();   // Q staging fully consumed; buffers free for K/V

    const __half* Kh = g_Khi + (size_t)bh * NSEQ * DH;
    const __half* Vh = g_Vhi + (size_t)bh * NSEQ * DH;
    const int lrow = tid >> 2, lq = tid & 3;
    const size_t loff = (size_t)lrow * DH + lq * 8;     // 8 fp16 = 16B
    const u32 sdst = lrow * ROWB + lq * 16;

    // tile 0 -> buffer 0 via cp.async
    cpa16(sb + KH_OFF + sdst, Kh + loff);
    cpa16(sb + VH_OFF + sdst, Vh + loff);
    CPA_COMMIT();
    CPA_WAIT0();
    __syncthreads();   // tile 0 visible

    const float* Ar = A + ((size_t)b * NSEQ + q0 + 16 * w + g) * NSEQ;

    float o[4][4] = {};
    float l0s = 0.f, l1s = 0.f;

    for (int kt = 0; kt < NKT; kt++) {
        const bool more = (kt + 1 < NKT);
        if (more) {
            size_t off2 = loff + (size_t)(kt + 1) * 64 * DH;
            u32 nb = sb + (u32)((kt + 1) & 1) * BUFB;
            cpa16(nb + KH_OFF + sdst, Kh + off2);
            cpa16(nb + VH_OFF + sdst, Vh + off2);
            CPA_COMMIT();
        }
        const u32 cb = sb + (u32)(kt & 1) * BUFB;     // compute buffer
        const int k0 = kt * 64;

        // ---- fused S -> PV per 16-key chunk, A software-pipelined ----
        float2 a01 = *(const float2*)(Ar + k0 + 2 * c);
        float2 a23 = *(const float2*)(Ar + 8 * NSEQ + k0 + 2 * c);
        #pragma unroll
        for (int t = 0; t < 4; t++) {
            u32 Ah[4];
            #pragma unroll
            for (int i = 0; i < 2; i++) {
                const int nt = 2 * t + i;
                u32 kaddr = cb + KH_OFF + (8 * nt + (lane & 7)) * ROWB + (lane >> 3) * 16;
                u32 kb0, kb1, kb2, kb3;
                ldsm4(kb0, kb1, kb2, kb3, kaddr);
                // two independent accumulation chains (depth 2 each)
                float sa[4] = {0.f, 0.f, 0.f, 0.f};
                float sc[4] = {0.f, 0.f, 0.f, 0.f};
                mma16816(sa, qh[0], kb0, kb1);
                mma16816(sc, ql[0], kb0, kb1);
                mma16816(sa, qh[1], kb2, kb3);
                mma16816(sc, ql[1], kb2, kb3);
                float2 na01, na23;
                if (nt < 7) {
                    na01 = *(const float2*)(Ar + k0 + 8 * (nt + 1) + 2 * c);
                    na23 = *(const float2*)(Ar + 8 * NSEQ + k0 + 8 * (nt + 1) + 2 * c);
                }
                float av[4] = { a01.x, a01.y, a23.x, a23.y };
                float p[4];
                #pragma unroll
                for (int e = 0; e < 4; e++) {
                    float a = av[e];
                    float bias;
                    if (fastp) {
                        bias = fmaf(a, a > 0.f ? cpl : cnl, b2hl);
                    } else {
                        float tt = 0.f;
                        #pragma unroll
                        for (int jj = 0; jj < 8; jj++) {
                            float u = fmaf(a, W1[jj], b1[jj]);
                            u = fmaxf(u, 0.01f * u);
                            tt = fmaf(W2[h * 8 + jj], u, tt);
                        }
                        bias = (tt + b2raw) * (float)LOG2E;
                    }
                    p[e] = ex2(sa[e] + sc[e] + bias);
                }
                l0s += p[0] + p[1];
                l1s += p[2] + p[3];
                Ah[2 * i]     = packh(p[0], p[1]);
                Ah[2 * i + 1] = packh(p[2], p[3]);
                a01 = na01; a23 = na23;
            }
            // PV chunk t (keys 16t..16t+15), single fp16 V
            u32 va0 = cb + VH_OFF + (16 * t + (lane & 7)) * ROWB + (lane >> 3) * 16;
            u32 va1 = va0 + 8 * ROWB;
            u32 v0a, v1a, v2a, v3a, v0b, v1b, v2b, v3b;
            ldsm4t(v0a, v1a, v2a, v3a, va0);
            ldsm4t(v0b, v1b, v2b, v3b, va1);
            mma16816(o[0], Ah, v0a, v0b);
            mma16816(o[1], Ah, v1a, v1b);
            mma16816(o[2], Ah, v2a, v2b);
            mma16816(o[3], Ah, v3a, v3b);
        }

        if (more) CPA_WAIT0();
        __syncthreads();
    }

    // ---- reduce row sums across the 4 lanes of each row, write O hi/lo ----
    l0s += __shfl_xor_sync(0xffffffffu, l0s, 1);
    l0s += __shfl_xor_sync(0xffffffffu, l0s, 2);
    l1s += __shfl_xor_sync(0xffffffffu, l1s, 1);
    l1s += __shfl_xor_sync(0xffffffffu, l1s, 2);
    float i0 = 1.0f / l0s, i1 = 1.0f / l1s;
    int r0g = q0 + 16 * w + g;
    size_t base0 = ((size_t)b * NSEQ + r0g) * DMODEL + h * DH;
    size_t base1 = base0 + 8 * DMODEL;
    #pragma unroll
    for (int ng = 0; ng < 4; ng++) {
        u32 lw, hw;
        hw = packsplith(o[ng][0] * i0, o[ng][1] * i0, lw);
        *(u32*)(g_Ohi + base0 + 8 * ng + 2 * c) = hw;
        *(u32*)(g_Olo + base0 + 8 * ng + 2 * c) = lw;
        hw = packsplith(o[ng][2] * i1, o[ng][3] * i1, lw);
        *(u32*)(g_Ohi + base1 + 8 * ng + 2 * c) = hw;
        *(u32*)(g_Olo + base1 + 8 * ng + 2 * c) = lw;
    }
}

extern "C" void kernel_launch(void* const* d_in, const int* in_sizes, int n_in,
                              void* d_out, int out_size)
{
    const float* x  = (const float*)d_in[0];
    const float* A  = (const float*)d_in[1];
    const float* Wq = (const float*)d_in[2];
    const float* bq = (const float*)d_in[3];
    const float* Wk = (const float*)d_in[4];
    const float* bk = (const float*)d_in[5];
    const float* Wv = (const float*)d_in[6];
    const float* bv = (const float*)d_in[7];
    const float* Wo = (const float*)d_in[8];
    const float* bo = (const float*)d_in[9];
    const float* W1 = (const float*)d_in[10];
    const float* b1 = (const float*)d_in[11];
    const float* W2 = (const float*)d_in[12];
    const float* b2 = (const float*)d_in[13];
    float* out = (float*)d_out;

    convert_w<<<dim3(128, 1, 4), 256>>>(Wq, Wk, Wv, Wo);
    proj_tc<<<dim3(DMODEL / 32, MROWS / 64, 3), 256>>>(x, bq, bk, bv, bo, out, 0);
    attn_mma<<<dim3(NSEQ / 128, NBH), 256>>>(A, W1, b1, W2, b2);
    proj_tc<<<dim3(DMODEL / 32, MROWS / 64, 1), 256>>>(x, bq, bk, bv, bo, out, 3);
}

// round 16
// speedup vs baseline: 1.2196x; 1.2196x over previous
#include <cuda_runtime.h>
#include <cuda_fp16.h>

#define BDIM 2
#define NSEQ 2048
#define DMODEL 256
#define HHEADS 8
#define DH 32
#define MROWS (BDIM*NSEQ)   // 4096
#define NBH (BDIM*HHEADS)   // 16

#define LOG2E 1.4426950408889634
#define QSCALE ((float)(1.4426950408889634/5.656854249492381))  // log2e/sqrt(32)

typedef unsigned long long u64;
typedef unsigned int u32;

// ---------------- scratch (__device__ globals; no allocations) --------------
__device__ __align__(16) __half g_Qhi[NBH*NSEQ*DH];
__device__ __align__(16) __half g_Qlo[NBH*NSEQ*DH];
__device__ __align__(16) __half g_Khi[NBH*NSEQ*DH];          // K: single fp16
__device__ __align__(16) __half g_Vhi[NBH*NSEQ*DH];          // V: single fp16
__device__ __align__(16) __half g_Ohi[MROWS*DMODEL];
__device__ __align__(16) __half g_Olo[MROWS*DMODEL];
__device__ __align__(16) __half g_wh[4*DMODEL*DMODEL];       // q,k,v,o  (single fp16)

// ---------------- helpers ---------------------------------------------------
__device__ __forceinline__ u32 smem_u32(const void* p) {
    u32 a; asm("{ .reg .u64 t; cvta.to.shared.u64 t, %1; cvt.u32.u64 %0, t; }" : "=r"(a) : "l"(p));
    return a;
}
__device__ __forceinline__ void ldsm4(u32 &r0, u32 &r1, u32 &r2, u32 &r3, u32 a) {
    asm volatile("ldmatrix.sync.aligned.m8n8.x4.shared.b16 {%0,%1,%2,%3}, [%4];"
                 : "=r"(r0), "=r"(r1), "=r"(r2), "=r"(r3) : "r"(a));
}
__device__ __forceinline__ void ldsm4t(u32 &r0, u32 &r1, u32 &r2, u32 &r3, u32 a) {
    asm volatile("ldmatrix.sync.aligned.m8n8.x4.trans.shared.b16 {%0,%1,%2,%3}, [%4];"
                 : "=r"(r0), "=r"(r1), "=r"(r2), "=r"(r3) : "r"(a));
}
__device__ __forceinline__ void mma16816(float* d, const u32* a, u32 b0, u32 b1) {
    asm volatile("mma.sync.aligned.m16n8k16.row.col.f32.f16.f16.f32 "
                 "{%0,%1,%2,%3}, {%4,%5,%6,%7}, {%8,%9}, {%0,%1,%2,%3};"
                 : "+f"(d[0]), "+f"(d[1]), "+f"(d[2]), "+f"(d[3])
                 : "r"(a[0]), "r"(a[1]), "r"(a[2]), "r"(a[3]), "r"(b0), "r"(b1));
}
__device__ __forceinline__ float ex2(float x) {
    float r; asm("ex2.approx.ftz.f32 %0, %1;" : "=f"(r) : "f"(x)); return r;
}
__device__ __forceinline__ u32 packh(float a, float b) {
    __half2 t = __floats2half2_rn(a, b);     // low = a
    return *(u32*)&t;
}
__device__ __forceinline__ u32 packsplith(float v0, float v1, u32 &lw) {
    u32 hw = packh(v0, v1);
    __half2 hv = *(__half2*)&hw;
    float e0 = __half2float(__low2half(hv));
    float e1 = __half2float(__high2half(hv));
    lw = packh(v0 - e0, v1 - e1);
    return hw;
}
__device__ __forceinline__ void cpa16(u32 dst, const void* src) {
    asm volatile("cp.async.cg.shared.global [%0], [%1], 16;" :: "r"(dst), "l"(src) : "memory");
}
#define CPA_COMMIT() asm volatile("cp.async.commit_group;" ::: "memory")
#define CPA_WAIT0()  asm volatile("cp.async.wait_group 0;" ::: "memory")

// ---------------------------------------------------------------------------
// Convert fp32 -> fp16 weights (single fp16), 4 matrices. grid (128,1,4).
// ---------------------------------------------------------------------------
__global__ __launch_bounds__(256) void convert_w(
    const float* __restrict__ Wq, const float* __restrict__ Wk,
    const float* __restrict__ Wv, const float* __restrict__ Wo)
{
    const int z = blockIdx.z;
    const float* src = (z == 0) ? Wq : (z == 1) ? Wk : (z == 2) ? Wv : Wo;
    __half* dh = g_wh + (size_t)z * DMODEL * DMODEL;
    int i = (blockIdx.x * 256 + threadIdx.x) * 2;
    if (i >= DMODEL * DMODEL) return;
    float2 v = *(const float2*)(src + i);
    *(u32*)(dh + i) = packh(v.x, v.y);
}

// ---------------------------------------------------------------------------
// Fused QKV projection: stages the X tile (hi/lo split) ONCE, runs it against
// Wq, Wk, Wv. BM=64, BN=64 per matrix, BK=32. 256 thr / 8 warps.
// grid (DMODEL/64, MROWS/64).
// ---------------------------------------------------------------------------
#define PRB 80       // smem row stride bytes (64B data + pad)
#define FXH 0
#define FXL 5120
#define FW  10240    // 3 x 5120 W regions follow

__global__ __launch_bounds__(256, 2) void proj_qkv(
    const float* __restrict__ x,
    const float* __restrict__ bq, const float* __restrict__ bk,
    const float* __restrict__ bv)
{
    __shared__ __align__(128) char sm[25600];
    const u32 sb = smem_u32(sm);
    const int tid = threadIdx.x, lane = tid & 31, w = tid >> 5;
    const int wr = w & 3, wc = w >> 2;
    const int row0 = blockIdx.y * 64, col0 = blockIdx.x * 64;
    const int xr = tid >> 2, xs = tid & 3;

    const float* px32 = x + (size_t)(row0 + xr) * DMODEL + xs * 8;
    const __half* pw0 = g_wh + 0 * DMODEL * DMODEL + (size_t)(col0 + xr) * DMODEL + xs * 8;
    const __half* pw1 = g_wh + 1 * DMODEL * DMODEL + (size_t)(col0 + xr) * DMODEL + xs * 8;
    const __half* pw2 = g_wh + 2 * DMODEL * DMODEL + (size_t)(col0 + xr) * DMODEL + xs * 8;

    uint4 rxh, rxl, rw0, rw1, rw2;
    {
        float4 f0 = *(const float4*)px32, f1 = *(const float4*)(px32 + 4);
        rxh.x = packsplith(f0.x, f0.y, rxl.x);
        rxh.y = packsplith(f0.z, f0.w, rxl.y);
        rxh.z = packsplith(f1.x, f1.y, rxl.z);
        rxh.w = packsplith(f1.z, f1.w, rxl.w);
    }
    rw0 = *(const uint4*)pw0;
    rw1 = *(const uint4*)pw1;
    rw2 = *(const uint4*)pw2;

    float acc[3][4][4] = {};
    const int j = lane >> 3, r = lane & 7;
    const u32 abase = sb + FXH + (u32)(16 * wr + (j & 1) * 8 + r) * PRB + (u32)(j >> 1) * 16;
    const u32 wbase = sb + FW + (u32)(32 * wc + (lane & 15)) * PRB + (u32)(lane >> 4) * 16;
    const u32 xdst = (u32)(xr * PRB + xs * 16);

    for (int kt = 0; kt < 8; kt++) {
        __syncthreads();
        *(uint4*)(sm + FXH + xdst) = rxh;
        *(uint4*)(sm + FXL + xdst) = rxl;
        *(uint4*)(sm + FW + 0 * 5120 + xdst) = rw0;
        *(uint4*)(sm + FW + 1 * 5120 + xdst) = rw1;
        *(uint4*)(sm + FW + 2 * 5120 + xdst) = rw2;
        __syncthreads();
        if (kt < 7) {
            int ko = (kt + 1) * 32;
            float4 f0 = *(const float4*)(px32 + ko), f1 = *(const float4*)(px32 + ko + 4);
            rxh.x = packsplith(f0.x, f0.y, rxl.x);
            rxh.y = packsplith(f0.z, f0.w, rxl.y);
            rxh.z = packsplith(f1.x, f1.y, rxl.z);
            rxh.w = packsplith(f1.z, f1.w, rxl.w);
            rw0 = *(const uint4*)(pw0 + ko);
            rw1 = *(const uint4*)(pw1 + ko);
            rw2 = *(const uint4*)(pw2 + ko);
        }
        u32 ah[2][4], al[2][4];
        ldsm4(ah[0][0], ah[0][1], ah[0][2], ah[0][3], abase);
        ldsm4(ah[1][0], ah[1][1], ah[1][2], ah[1][3], abase + 32);
        ldsm4(al[0][0], al[0][1], al[0][2], al[0][3], abase + (FXL - FXH));
        ldsm4(al[1][0], al[1][1], al[1][2], al[1][3], abase + (FXL - FXH) + 32);
        #pragma unroll
        for (int m = 0; m < 3; m++) {
            #pragma unroll
            for (int ng = 0; ng < 2; ng++) {
                #pragma unroll
                for (int kc = 0; kc < 2; kc++) {
                    u32 wb = wbase + (u32)(m * 5120) + (u32)(16 * ng) * PRB + kc * 32;
                    u32 h0, h1, h2, h3;
                    ldsm4(h0, h1, h2, h3, wb);
                    mma16816(acc[m][2 * ng],     ah[kc], h0, h2);
                    mma16816(acc[m][2 * ng],     al[kc], h0, h2);
                    mma16816(acc[m][2 * ng + 1], ah[kc], h1, h3);
                    mma16816(acc[m][2 * ng + 1], al[kc], h1, h3);
                }
            }
        }
    }

    // epilogue
    const int g = lane >> 2, c = lane & 3;
    const int m0 = row0 + 16 * wr + g;
    #pragma unroll
    for (int m = 0; m < 3; m++) {
        const float* bias = (m == 0) ? bq : (m == 1) ? bk : bv;
        #pragma unroll
        for (int half = 0; half < 2; half++) {
            int mm = m0 + 8 * half;
            int bb = mm >> 11, n = mm & (NSEQ - 1);
            #pragma unroll
            for (int nn = 0; nn < 4; nn++) {
                int col = col0 + 32 * wc + 8 * nn + 2 * c;
                float v0 = acc[m][nn][2 * half + 0] + bias[col];
                float v1 = acc[m][nn][2 * half + 1] + bias[col + 1];
                int hh = col >> 5, d = col & 31;
                size_t idx = (((size_t)(bb * HHEADS + hh)) * NSEQ + n) * DH + d;
                if (m == 1) {
                    *(u32*)(g_Khi + idx) = packh(v0, v1);
                } else if (m == 2) {
                    *(u32*)(g_Vhi + idx) = packh(v0, v1);
                } else {
                    v0 *= QSCALE; v1 *= QSCALE;
                    u32 lw, hw = packsplith(v0, v1, lw);
                    *(u32*)(g_Qhi + idx) = hw;
                    *(u32*)(g_Qlo + idx) = lw;
                }
            }
        }
    }
}

// ---------------------------------------------------------------------------
// Output projection: out = O @ Wo^T + bo, fp16 2-term (Ohi+Olo)*Wo.
// BM=64, BN=64, BK=32. 256 thr / 8 warps. (round-14 proven version)
// ---------------------------------------------------------------------------
#define PXH 0
#define PXL 5120
#define PWH 10240

__global__ __launch_bounds__(256, 3) void proj_out(
    const float* __restrict__ bo, float* __restrict__ outf)
{
    __shared__ __align__(128) char sm[15360];
    const u32 sb = smem_u32(sm);
    const __half* Wh = g_wh + (size_t)3 * DMODEL * DMODEL;

    const int tid = threadIdx.x, lane = tid & 31, w = tid >> 5;
    const int wr = w & 3, wc = w >> 2;
    const int row0 = blockIdx.y * 64, col0 = blockIdx.x * 64;

    const int xr = tid >> 2, xs = tid & 3;

    const __half* poh = g_Ohi + (size_t)(row0 + xr) * DMODEL + xs * 8;
    const __half* pol = g_Olo + (size_t)(row0 + xr) * DMODEL + xs * 8;
    const __half* pwh = Wh + (size_t)(col0 + xr) * DMODEL + xs * 8;

    uint4 rxh = *(const uint4*)poh, rxl = *(const uint4*)pol;
    uint4 rwh = *(const uint4*)pwh;

    float acc[4][4] = {};
    const int j = lane >> 3, r = lane & 7;
    const u32 abase = sb + PXH + (u32)(16 * wr + (j & 1) * 8 + r) * PRB + (u32)(j >> 1) * 16;
    const u32 wbase = sb + PWH + (u32)(32 * wc + (lane & 15)) * PRB + (u32)(lane >> 4) * 16;

    for (int kt = 0; kt < 8; kt++) {
        __syncthreads();
        *(uint4*)(sm + PXH + xr * PRB + xs * 16) = rxh;
        *(uint4*)(sm + PXL + xr * PRB + xs * 16) = rxl;
        *(uint4*)(sm + PWH + xr * PRB + xs * 16) = rwh;
        __syncthreads();
        if (kt < 7) {
            int ko = (kt + 1) * 32;
            rxh = *(const uint4*)(poh + ko); rxl = *(const uint4*)(pol + ko);
            rwh = *(const uint4*)(pwh + ko);
        }
        u32 ah[2][4], al[2][4];
        ldsm4(ah[0][0], ah[0][1], ah[0][2], ah[0][3], abase);
        ldsm4(ah[1][0], ah[1][1], ah[1][2], ah[1][3], abase + 32);
        ldsm4(al[0][0], al[0][1], al[0][2], al[0][3], abase + (PXL - PXH));
        ldsm4(al[1][0], al[1][1], al[1][2], al[1][3], abase + (PXL - PXH) + 32);
        #pragma unroll
        for (int ng = 0; ng < 2; ng++) {
            #pragma unroll
            for (int kc = 0; kc < 2; kc++) {
                u32 wb = wbase + (u32)(16 * ng) * PRB + kc * 32;
                u32 h0, h1, h2, h3;
                ldsm4(h0, h1, h2, h3, wb);
                mma16816(acc[2 * ng],     ah[kc], h0, h2);
                mma16816(acc[2 * ng],     al[kc], h0, h2);
                mma16816(acc[2 * ng + 1], ah[kc], h1, h3);
                mma16816(acc[2 * ng + 1], al[kc], h1, h3);
            }
        }
    }

    const int g = lane >> 2, c = lane & 3;
    const int m0 = row0 + 16 * wr + g;
    #pragma unroll
    for (int half = 0; half < 2; half++) {
        int m = m0 + 8 * half;
        #pragma unroll
        for (int nn = 0; nn < 4; nn++) {
            int col = col0 + 32 * wc + 8 * nn + 2 * c;
            float v0 = acc[nn][2 * half + 0] + bo[col];
            float v1 = acc[nn][2 * half + 1] + bo[col + 1];
            *(float2*)(outf + (size_t)m * DMODEL + col) = make_float2(v0, v1);
        }
    }
}

// ---------------------------------------------------------------------------
// mma.sync flash attention, fp16. S = (Qhi+Qlo)*Khi; PV = Phi*Vhi.
// cp.async K/V staging into double buffer; fused S->PV per 16-key chunk;
// A-tile software pipelined in registers. One __syncthreads per k-tile.
// Grid (16 q-tiles, 16 bh), 256 threads / 8 warps; warp owns 16 query rows.
// (round-14 proven version, unchanged)
// ---------------------------------------------------------------------------
#define ROWB 80
#define BUFB 10240          // bytes per K/V buffer (K 5120 + V 5120)
#define KH_OFF 0
#define VH_OFF 5120
#define NKT (NSEQ/64)       // 32 k-tiles

__global__ __launch_bounds__(256, 2) void attn_mma(
    const float* __restrict__ A,
    const float* __restrict__ W1, const float* __restrict__ b1,
    const float* __restrict__ W2, const float* __restrict__ b2)
{
    __shared__ __align__(128) char smem[2 * BUFB];
    const u32 sb = smem_u32(smem);
    const int tid = threadIdx.x;
    const int lane = tid & 31, w = tid >> 5;
    const int bh = blockIdx.y, b = bh >> 3, h = bh & 7;
    const int q0 = blockIdx.x * 128;
    const int g = lane >> 2, c = lane & 3;

    // bias MLP coefficients (log2 domain)
    bool fastp = true;
    float cpl = 0.f, cnl = 0.f;
    #pragma unroll
    for (int j = 0; j < 8; j++) {
        float w1 = W1[j], w2v = W2[h * 8 + j];
        fastp = fastp && (b1[j] == 0.0f);
        float cc = w2v * w1;
        cpl += cc * (w1 > 0.f ? 1.0f : 0.01f);
        cnl += cc * (w1 < 0.f ? 1.0f : 0.01f);
    }
    const float b2raw = b2[h];
    const float b2hl = b2raw * (float)LOG2E;
    cpl *= (float)LOG2E; cnl *= (float)LOG2E;

    // ---- stage Q: QH -> buffer0, QL -> buffer1; consume to regs ----
    {
        int row = tid >> 1, seg = tid & 1;
        const uint4* sh = (const uint4*)(g_Qhi + ((size_t)bh * NSEQ + q0 + row) * DH + seg * 16);
        const uint4* sl = (const uint4*)(g_Qlo + ((size_t)bh * NSEQ + q0 + row) * DH + seg * 16);
        uint4 h0 = sh[0], h1 = sh[1];
        uint4 l0 = sl[0], l1 = sl[1];
        char* d0 = smem + row * ROWB + seg * 32;
        *(uint4*)d0 = h0; *(uint4*)(d0 + 16) = h1;
        char* d1 = smem + BUFB + row * ROWB + seg * 32;
        *(uint4*)d1 = l0; *(uint4*)(d1 + 16) = l1;
    }
    __syncthreads();
    u32 qh[2][4], ql[2][4];
    {
        int j = lane >> 3, r = lane & 7;
        int qrow = 16 * w + (j & 1) * 8 + r;
        u32 base = sb + qrow * ROWB + (u32)(j >> 1) * 16;
        ldsm4(qh[0][0], qh[0][1], qh[0][2], qh[0][3], base);
        ldsm4(qh[1][0], qh[1][1], qh[1][2], qh[1][3], base + 32);
        ldsm4(ql[0][0], ql[0][1], ql[0][2], ql[0][3], base + BUFB);
        ldsm4(ql[1][0], ql[1][1], ql[1][2], ql[1][3], base + BUFB + 32);
    }
    __syncthreads();   // Q staging fully consumed; buffers free for K/V

    const __half* Kh = g_Khi + (size_t)bh * NSEQ * DH;
    const __half* Vh = g_Vhi + (size_t)bh * NSEQ * DH;
    const int lrow = tid >> 2, lq = tid & 3;
    const size_t loff = (size_t)lrow * DH + lq * 8;     // 8 fp16 = 16B
    const u32 sdst = lrow * ROWB + lq * 16;

    // tile 0 -> buffer 0 via cp.async
    cpa16(sb + KH_OFF + sdst, Kh + loff);
    cpa16(sb + VH_OFF + sdst, Vh + loff);
    CPA_COMMIT();
    CPA_WAIT0();
    __syncthreads();   // tile 0 visible

    const float* Ar = A + ((size_t)b * NSEQ + q0 + 16 * w + g) * NSEQ;

    float o[4][4] = {};
    float l0s = 0.f, l1s = 0.f;

    for (int kt = 0; kt < NKT; kt++) {
        const bool more = (kt + 1 < NKT);
        if (more) {
            size_t off2 = loff + (size_t)(kt + 1) * 64 * DH;
            u32 nb = sb + (u32)((kt + 1) & 1) * BUFB;
            cpa16(nb + KH_OFF + sdst, Kh + off2);
            cpa16(nb + VH_OFF + sdst, Vh + off2);
            CPA_COMMIT();
        }
        const u32 cb = sb + (u32)(kt & 1) * BUFB;     // compute buffer
        const int k0 = kt * 64;

        // ---- fused S -> PV per 16-key chunk, A software-pipelined ----
        float2 a01 = *(const float2*)(Ar + k0 + 2 * c);
        float2 a23 = *(const float2*)(Ar + 8 * NSEQ + k0 + 2 * c);
        #pragma unroll
        for (int t = 0; t < 4; t++) {
            u32 Ah[4];
            #pragma unroll
            for (int i = 0; i < 2; i++) {
                const int nt = 2 * t + i;
                u32 kaddr = cb + KH_OFF + (8 * nt + (lane & 7)) * ROWB + (lane >> 3) * 16;
                u32 kb0, kb1, kb2, kb3;
                ldsm4(kb0, kb1, kb2, kb3, kaddr);
                float s[4] = {0.f, 0.f, 0.f, 0.f};
                mma16816(s, qh[0], kb0, kb1);
                mma16816(s, qh[1], kb2, kb3);
                mma16816(s, ql[0], kb0, kb1);
                mma16816(s, ql[1], kb2, kb3);
                float2 na01, na23;
                if (nt < 7) {
                    na01 = *(const float2*)(Ar + k0 + 8 * (nt + 1) + 2 * c);
                    na23 = *(const float2*)(Ar + 8 * NSEQ + k0 + 8 * (nt + 1) + 2 * c);
                }
                float av[4] = { a01.x, a01.y, a23.x, a23.y };
                float p[4];
                #pragma unroll
                for (int e = 0; e < 4; e++) {
                    float a = av[e];
                    float bias;
                    if (fastp) {
                        bias = fmaf(a, a > 0.f ? cpl : cnl, b2hl);
                    } else {
                        float tt = 0.f;
                        #pragma unroll
                        for (int jj = 0; jj < 8; jj++) {
                            float u = fmaf(a, W1[jj], b1[jj]);
                            u = fmaxf(u, 0.01f * u);
                            tt = fmaf(W2[h * 8 + jj], u, tt);
                        }
                        bias = (tt + b2raw) * (float)LOG2E;
                    }
                    p[e] = ex2(s[e] + bias);
                }
                l0s += p[0] + p[1];
                l1s += p[2] + p[3];
                Ah[2 * i]     = packh(p[0], p[1]);
                Ah[2 * i + 1] = packh(p[2], p[3]);
                a01 = na01; a23 = na23;
            }
            // PV chunk t (keys 16t..16t+15), single fp16 V
            u32 va0 = cb + VH_OFF + (16 * t + (lane & 7)) * ROWB + (lane >> 3) * 16;
            u32 va1 = va0 + 8 * ROWB;
            u32 v0a, v1a, v2a, v3a, v0b, v1b, v2b, v3b;
            ldsm4t(v0a, v1a, v2a, v3a, va0);
            ldsm4t(v0b, v1b, v2b, v3b, va1);
            mma16816(o[0], Ah, v0a, v0b);
            mma16816(o[1], Ah, v1a, v1b);
            mma16816(o[2], Ah, v2a, v2b);
            mma16816(o[3], Ah, v3a, v3b);
        }

        if (more) CPA_WAIT0();
        __syncthreads();
    }

    // ---- reduce row sums across the 4 lanes of each row, write O hi/lo ----
    l0s += __shfl_xor_sync(0xffffffffu, l0s, 1);
    l0s += __shfl_xor_sync(0xffffffffu, l0s, 2);
    l1s += __shfl_xor_sync(0xffffffffu, l1s, 1);
    l1s += __shfl_xor_sync(0xffffffffu, l1s, 2);
    float i0 = 1.0f / l0s, i1 = 1.0f / l1s;
    int r0g = q0 + 16 * w + g;
    size_t base0 = ((size_t)b * NSEQ + r0g) * DMODEL + h * DH;
    size_t base1 = base0 + 8 * DMODEL;
    #pragma unroll
    for (int ng = 0; ng < 4; ng++) {
        u32 lw, hw;
        hw = packsplith(o[ng][0] * i0, o[ng][1] * i0, lw);
        *(u32*)(g_Ohi + base0 + 8 * ng + 2 * c) = hw;
        *(u32*)(g_Olo + base0 + 8 * ng + 2 * c) = lw;
        hw = packsplith(o[ng][2] * i1, o[ng][3] * i1, lw);
        *(u32*)(g_Ohi + base1 + 8 * ng + 2 * c) = hw;
        *(u32*)(g_Olo + base1 + 8 * ng + 2 * c) = lw;
    }
}

extern "C" void kernel_launch(void* const* d_in, const int* in_sizes, int n_in,
                              void* d_out, int out_size)
{
    const float* x  = (const float*)d_in[0];
    const float* A  = (const float*)d_in[1];
    const float* Wq = (const float*)d_in[2];
    const float* bq = (const float*)d_in[3];
    const float* Wk = (const float*)d_in[4];
    const float* bk = (const float*)d_in[5];
    const float* Wv = (const float*)d_in[6];
    const float* bv = (const float*)d_in[7];
    const float* Wo = (const float*)d_in[8];
    const float* bo = (const float*)d_in[9];
    const float* W1 = (const float*)d_in[10];
    const float* b1 = (const float*)d_in[11];
    const float* W2 = (const float*)d_in[12];
    const float* b2 = (const float*)d_in[13];
    float* out = (float*)d_out;

    convert_w<<<dim3(128, 1, 4), 256>>>(Wq, Wk, Wv, Wo);
    proj_qkv<<<dim3(DMODEL / 64, MROWS / 64), 256>>>(x, bq, bk, bv);
    attn_mma<<<dim3(NSEQ / 128, NBH), 256>>>(A, W1, b1, W2, b2);
    proj_out<<<dim3(DMODEL / 64, MROWS / 64), 256>>>(bo, out);
}